// round 5
// baseline (speedup 1.0000x reference)
#include <cuda_runtime.h>
#include <cuda_bf16.h>

#define N_USERS 50000
#define N_ITEMS 50000
#define N_NODES 100000
#define NNZ     1600000
#define EMB     64
#define N_LAYERS 3
#define BATCH   4096
#define REG_L2  1e-5f

#define SCAN_CHUNK 512
#define NBLK ((N_NODES + SCAN_CHUNK - 1) / SCAN_CHUNK)   // 196
#define ROWSTRIDE (EMB * (N_LAYERS + 1))                 // 256

// all_emb: [node][256]; slice k = cols [64k,64k+64). Slice 0 = raw ego,
// slices 1..3 = UNNORMALIZED activations; g_norm = inverse norms.
__device__ float g_all [(size_t)N_NODES * ROWSTRIDE];    // 102.4 MB
__device__ float g_side[(size_t)N_NODES * EMB];          // 25.6 MB
__device__ float g_norm[(size_t)N_LAYERS * N_NODES];     // 1.2 MB
__device__ float g_acc[2];
// bf16 mirror of CURRENT ego slice: gather table for the SpMM (halves L2 traffic)
__device__ __nv_bfloat16 g_ego16[(size_t)N_NODES * EMB]; // 12.8 MB

// CSR build scratch
__device__ int  g_cnt[N_NODES];
__device__ int  g_row_ptr[N_NODES + 1];
__device__ int  g_cur[N_NODES];
__device__ int  g_bsum[NBLK];
__device__ int2 g_csr[NNZ];                              // {col, val bits}

// ---------------------------------------------------------------------------
__global__ void init_kernel(const float* __restrict__ ue, const float* __restrict__ ie) {
    int t = blockIdx.x * 256 + threadIdx.x;              // N_NODES*16 threads
    if (t < 2) g_acc[t] = 0.f;
    int node = t >> 4, q = t & 15;
    const float* src = (node < N_USERS) ? (ue + (size_t)node * EMB)
                                        : (ie + (size_t)(node - N_USERS) * EMB);
    float4 v = *(const float4*)(src + q * 4);
    *(float4*)(g_all + (size_t)node * ROWSTRIDE + q * 4) = v;
    __nv_bfloat162* b = (__nv_bfloat162*)(g_ego16 + (size_t)node * EMB + q * 4);
    b[0] = __floats2bfloat162_rn(v.x, v.y);
    b[1] = __floats2bfloat162_rn(v.z, v.w);
}

// ---------------------------------------------------------------------------
// CSR build: histogram -> 2-level exclusive scan -> scatter
// ---------------------------------------------------------------------------
__global__ void hist_kernel(const int* __restrict__ row) {
    int t = blockIdx.x * 256 + threadIdx.x;
    if (t < NNZ) atomicAdd(&g_cnt[__ldg(row + t)], 1);
}

__global__ void scan1_kernel() {
    __shared__ int shw[16];
    int t = threadIdx.x;                                  // 512 threads
    int i = blockIdx.x * SCAN_CHUNK + t;
    int v = (i < N_NODES) ? g_cnt[i] : 0;
    #pragma unroll
    for (int o = 16; o; o >>= 1) v += __shfl_xor_sync(0xffffffffu, v, o);
    if ((t & 31) == 0) shw[t >> 5] = v;
    __syncthreads();
    if (t < 32) {
        int s = (t < 16) ? shw[t] : 0;
        #pragma unroll
        for (int o = 8; o; o >>= 1) s += __shfl_xor_sync(0xffffffffu, s, o);
        if (t == 0) g_bsum[blockIdx.x] = s;
    }
}

__global__ void scanB_kernel() {
    __shared__ int shw[8];
    int t = threadIdx.x;                                  // 256 threads
    int lane = t & 31, w = t >> 5;
    int v = (t < NBLK) ? g_bsum[t] : 0;
    int inc = v;
    #pragma unroll
    for (int o = 1; o < 32; o <<= 1) {
        int n = __shfl_up_sync(0xffffffffu, inc, o);
        if (lane >= o) inc += n;
    }
    if (lane == 31) shw[w] = inc;
    __syncthreads();
    if (t < 32) {
        int s = (t < 8) ? shw[t] : 0;
        #pragma unroll
        for (int o = 1; o < 8; o <<= 1) {
            int n = __shfl_up_sync(0xffffffffu, s, o);
            if (lane >= o) s += n;
        }
        if (t < 8) shw[t] = s;
    }
    __syncthreads();
    int base = (w > 0) ? shw[w - 1] : 0;
    if (t < NBLK) g_bsum[t] = base + inc - v;
}

__global__ void scan2_kernel() {
    __shared__ int shw[16];
    int t = threadIdx.x;                                  // 512 threads
    int lane = t & 31, w = t >> 5;
    int i = blockIdx.x * SCAN_CHUNK + t;
    int v = (i < N_NODES) ? g_cnt[i] : 0;
    int inc = v;
    #pragma unroll
    for (int o = 1; o < 32; o <<= 1) {
        int n = __shfl_up_sync(0xffffffffu, inc, o);
        if (lane >= o) inc += n;
    }
    if (lane == 31) shw[w] = inc;
    __syncthreads();
    if (t < 32) {
        int s = (t < 16) ? shw[t] : 0;
        #pragma unroll
        for (int o = 1; o < 16; o <<= 1) {
            int n = __shfl_up_sync(0xffffffffu, s, o);
            if (lane >= o) s += n;
        }
        if (t < 16) shw[t] = s;
    }
    __syncthreads();
    int base = ((w > 0) ? shw[w - 1] : 0) + g_bsum[blockIdx.x];
    int ex = base + inc - v;
    if (i < N_NODES) { g_row_ptr[i] = ex; g_cur[i] = ex; }
    if (i == N_NODES) g_row_ptr[N_NODES] = NNZ;
}

__global__ void scatter_kernel(const int* __restrict__ row,
                               const int* __restrict__ col,
                               const float* __restrict__ val) {
    int t = blockIdx.x * 256 + threadIdx.x;
    if (t >= NNZ) return;
    int r = __ldg(row + t);
    int pos = atomicAdd(&g_cur[r], 1);
    g_csr[pos] = make_int2(__ldg(col + t), __float_as_int(__ldg(val + t)));
}

// ---------------------------------------------------------------------------
// SpMM (CSR gather): one warp per row, zero smem, MLP-4 gather from the
// bf16 ego mirror (128B per edge = 1 cache line); fp32 accumulation.
// ---------------------------------------------------------------------------
__global__ void __launch_bounds__(256) spmm_csr_kernel() {
    int gt = blockIdx.x * 256 + threadIdx.x;
    int row = gt >> 5, lane = gt & 31;
    if (row >= N_NODES) return;
    const __nv_bfloat162* ego = (const __nv_bfloat162*)g_ego16;   // [node*32 + lane]
    int beg = g_row_ptr[row], end = g_row_ptr[row + 1];
    float2 acc = make_float2(0.f, 0.f);
    int e = beg;
    for (; e + 4 <= end; e += 4) {
        int2 cv0 = __ldg(&g_csr[e]);
        int2 cv1 = __ldg(&g_csr[e + 1]);
        int2 cv2 = __ldg(&g_csr[e + 2]);
        int2 cv3 = __ldg(&g_csr[e + 3]);
        __nv_bfloat162 x0 = __ldg(ego + (size_t)cv0.x * 32 + lane);
        __nv_bfloat162 x1 = __ldg(ego + (size_t)cv1.x * 32 + lane);
        __nv_bfloat162 x2 = __ldg(ego + (size_t)cv2.x * 32 + lane);
        __nv_bfloat162 x3 = __ldg(ego + (size_t)cv3.x * 32 + lane);
        float2 a0 = __bfloat1622float2(x0);
        float2 a1 = __bfloat1622float2(x1);
        float2 a2 = __bfloat1622float2(x2);
        float2 a3 = __bfloat1622float2(x3);
        float v0 = __int_as_float(cv0.y), v1 = __int_as_float(cv1.y);
        float v2 = __int_as_float(cv2.y), v3 = __int_as_float(cv3.y);
        acc.x += v0 * a0.x + v1 * a1.x + v2 * a2.x + v3 * a3.x;
        acc.y += v0 * a0.y + v1 * a1.y + v2 * a2.y + v3 * a3.y;
    }
    for (; e < end; e++) {
        int2 cv = __ldg(&g_csr[e]);
        float v = __int_as_float(cv.y);
        float2 a = __bfloat1622float2(__ldg(ego + (size_t)cv.x * 32 + lane));
        acc.x += v * a.x;
        acc.y += v * a.y;
    }
    *(float2*)(g_side + (size_t)row * EMB + lane * 2) = acc;
}

// ---------------------------------------------------------------------------
// Transform: act = leaky_relu(side@Wg + ego*(side-ego)@Wb + b)
// Writes UNNORMALIZED act to g_all slice k+1, inverse norm to g_norm,
// and refreshes the bf16 ego mirror for the next layer's SpMM.
// ---------------------------------------------------------------------------
#define TR_SMEM (2048 * 16 + 64 * 4 + 4096 * 8)

__global__ void __launch_bounds__(256) transform_kernel(
        const float* __restrict__ Wg, const float* __restrict__ bg,
        const float* __restrict__ Wb, const float* __restrict__ bb, int k) {
    extern __shared__ float sh[];
    float4* shW4 = (float4*)sh;
    float*  shB  = sh + 2048 * 4;
    float2* shX  = (float2*)(shB + 64);

    int tid = threadIdx.x;
    const float* Wg_k = Wg + k * 4096;
    const float* Wb_k = Wb + k * 4096;
    #pragma unroll
    for (int idx = tid; idx < 2048; idx += 256) {
        int j = idx >> 5, l = idx & 31;
        float2 g = *(const float2*)(Wg_k + j * 64 + l * 2);
        float2 b = *(const float2*)(Wb_k + j * 64 + l * 2);
        shW4[idx] = make_float4(g.x, g.y, b.x, b.y);
    }
    if (tid < 64) shB[tid] = bg[k * 64 + tid] + bb[k * 64 + tid];
    __syncthreads();

    int warp = tid >> 5, lane = tid & 31;
    int rowbase = (blockIdx.x * 8 + warp) * 8;
    float2* shXw = shX + warp * 512;
    const float* ego = g_all + k * EMB;

    #pragma unroll
    for (int r = 0; r < 8; r++) {
        int row = rowbase + r;
        float2 x1 = make_float2(0.f, 0.f), x2 = make_float2(0.f, 0.f);
        if (row < N_NODES) {
            float2 s = *(const float2*)(g_side + (size_t)row * EMB + lane * 2);
            float2 e = *(const float2*)(ego + (size_t)row * ROWSTRIDE + lane * 2);
            x1 = s;
            x2 = make_float2(e.x * (s.x - e.x), e.y * (s.y - e.y));
        }
        ((float4*)(shXw + r * 64))[lane] = make_float4(x1.x, x2.x, x1.y, x2.y);
    }
    __syncwarp();

    float bx = shB[2 * lane], by = shB[2 * lane + 1];
    float2 acc[8];
    #pragma unroll
    for (int r = 0; r < 8; r++) acc[r] = make_float2(bx, by);

    #pragma unroll 4
    for (int j = 0; j < 64; j++) {
        float4 w = shW4[j * 32 + lane];
        #pragma unroll
        for (int r = 0; r < 8; r++) {
            float2 x = shXw[r * 64 + j];
            acc[r].x += x.x * w.x + x.y * w.z;
            acc[r].y += x.x * w.y + x.y * w.w;
        }
    }

    #pragma unroll
    for (int r = 0; r < 8; r++) {
        int row = rowbase + r;
        float v0 = acc[r].x, v1 = acc[r].y;
        v0 = (v0 >= 0.f) ? v0 : 0.01f * v0;
        v1 = (v1 >= 0.f) ? v1 : 0.01f * v1;
        float p = v0 * v0 + v1 * v1;
        #pragma unroll
        for (int o = 16; o; o >>= 1) p += __shfl_xor_sync(0xffffffffu, p, o);
        float inv = 1.f / fmaxf(sqrtf(p), 1e-12f);
        if (row < N_NODES) {
            *(float2*)(g_all + (size_t)row * ROWSTRIDE + (k + 1) * EMB + lane * 2)
                = make_float2(v0, v1);
            if (k < N_LAYERS - 1)
                *(__nv_bfloat162*)(g_ego16 + (size_t)row * EMB + lane * 2)
                    = __floats2bfloat162_rn(v0, v1);
            if (lane == 0) g_norm[(size_t)k * N_NODES + row] = inv;
        }
    }
}

// ---------------------------------------------------------------------------
// BPR loss: one warp per batch element; norms applied on the fly.
// ---------------------------------------------------------------------------
__global__ void loss_kernel(const int* __restrict__ u,
                            const int* __restrict__ ii,
                            const int* __restrict__ jj) {
    int warp = threadIdx.x >> 5, lane = threadIdx.x & 31;
    int b = blockIdx.x * 4 + warp;
    int un = u[b], pn = N_USERS + ii[b], nn = N_USERS + jj[b];
    const float* ur = g_all + (size_t)un * ROWSTRIDE;
    const float* pr = g_all + (size_t)pn * ROWSTRIDE;
    const float* nr = g_all + (size_t)nn * ROWSTRIDE;

    float iu[4], ip[4], in_[4];
    iu[0] = ip[0] = in_[0] = 1.f;
    #pragma unroll
    for (int s = 1; s < 4; s++) {
        iu[s]  = __ldg(&g_norm[(size_t)(s - 1) * N_NODES + un]);
        ip[s]  = __ldg(&g_norm[(size_t)(s - 1) * N_NODES + pn]);
        in_[s] = __ldg(&g_norm[(size_t)(s - 1) * N_NODES + nn]);
    }

    float dui = 0.f, duj = 0.f, l2 = 0.f;
    #pragma unroll
    for (int s = 0; s < 4; s++) {
        float2 uv = *(const float2*)(ur + s * EMB + lane * 2);
        float2 pv = *(const float2*)(pr + s * EMB + lane * 2);
        float2 nv = *(const float2*)(nr + s * EMB + lane * 2);
        uv.x *= iu[s];  uv.y *= iu[s];
        pv.x *= ip[s];  pv.y *= ip[s];
        nv.x *= in_[s]; nv.y *= in_[s];
        dui += uv.x * pv.x + uv.y * pv.y;
        duj += uv.x * nv.x + uv.y * nv.y;
        l2  += uv.x * uv.x + uv.y * uv.y
             + pv.x * pv.x + pv.y * pv.y
             + nv.x * nv.x + nv.y * nv.y;
    }
    #pragma unroll
    for (int o = 16; o; o >>= 1) {
        dui += __shfl_xor_sync(0xffffffffu, dui, o);
        duj += __shfl_xor_sync(0xffffffffu, duj, o);
        l2  += __shfl_xor_sync(0xffffffffu, l2,  o);
    }
    if (lane == 0) {
        float diff = dui - duj;
        float lp = fminf(diff, 0.f) - log1pf(expf(-fabsf(diff)));
        atomicAdd(&g_acc[0], lp);
        atomicAdd(&g_acc[1], 0.5f * l2);
    }
}

__global__ void finalize_kernel(float* out) {
    out[0] = -g_acc[0] / (float)BATCH + REG_L2 * (g_acc[1] / (float)BATCH);
}

// ---------------------------------------------------------------------------
extern "C" void kernel_launch(void* const* d_in, const int* in_sizes, int n_in,
                              void* d_out, int out_size) {
    const float* user_emb = (const float*)d_in[0];
    const float* item_emb = (const float*)d_in[1];
    const float* W_gc     = (const float*)d_in[2];
    const float* b_gc     = (const float*)d_in[3];
    const float* W_bi     = (const float*)d_in[4];
    const float* b_bi     = (const float*)d_in[5];
    const float* adj_val  = (const float*)d_in[6];
    const int*   adj_row  = (const int*)d_in[7];
    const int*   adj_col  = (const int*)d_in[8];
    const int*   u        = (const int*)d_in[9];
    const int*   i        = (const int*)d_in[10];
    const int*   j        = (const int*)d_in[11];
    float* out = (float*)d_out;

    // One-time infra (streams/events are not device memory; created once)
    static cudaStream_t s2 = nullptr;
    static cudaEvent_t evFork = nullptr, evJoin = nullptr;
    if (s2 == nullptr) {
        cudaStreamCreateWithFlags(&s2, cudaStreamNonBlocking);
        cudaEventCreateWithFlags(&evFork, cudaEventDisableTiming);
        cudaEventCreateWithFlags(&evJoin, cudaEventDisableTiming);
        cudaFuncSetAttribute(transform_kernel,
                             cudaFuncAttributeMaxDynamicSharedMemorySize, TR_SMEM);
    }

    void* cnt_ptr = nullptr;
    cudaGetSymbolAddress(&cnt_ptr, g_cnt);

    // Fork: init on s2, CSR build on stream 0 (independent work)
    cudaEventRecord(evFork, 0);
    cudaStreamWaitEvent(s2, evFork, 0);
    init_kernel<<<(N_NODES * 16) / 256, 256, 0, s2>>>(user_emb, item_emb);
    cudaEventRecord(evJoin, s2);

    cudaMemsetAsync(cnt_ptr, 0, (size_t)N_NODES * sizeof(int), 0);
    hist_kernel<<<(NNZ + 255) / 256, 256>>>(adj_row);
    scan1_kernel<<<NBLK, SCAN_CHUNK>>>();
    scanB_kernel<<<1, 256>>>();
    scan2_kernel<<<NBLK, SCAN_CHUNK>>>();
    scatter_kernel<<<(NNZ + 255) / 256, 256>>>(adj_row, adj_col, adj_val);

    // Join before layers
    cudaStreamWaitEvent(0, evJoin, 0);

    for (int k = 0; k < N_LAYERS; k++) {
        spmm_csr_kernel<<<(N_NODES * 32 + 255) / 256, 256>>>();
        transform_kernel<<<(N_NODES + 63) / 64, 256, TR_SMEM>>>(W_gc, b_gc, W_bi, b_bi, k);
    }

    loss_kernel<<<BATCH / 4, 128>>>(u, i, j);
    finalize_kernel<<<1, 1>>>(out);
}

// round 6
// speedup vs baseline: 1.0525x; 1.0525x over previous
#include <cuda_runtime.h>
#include <cuda_bf16.h>

#define N_USERS 50000
#define N_ITEMS 50000
#define N_NODES 100000
#define NNZ     1600000
#define EMB     64
#define N_LAYERS 3
#define BATCH   4096
#define REG_L2  1e-5f

#define SCAN_CHUNK 512
#define NBLK ((N_NODES + SCAN_CHUNK - 1) / SCAN_CHUNK)   // 196
#define ROWSTRIDE (EMB * (N_LAYERS + 1))                 // 256

// all_emb: [node][256]; slice k = cols [64k,64k+64). Slice 0 = raw ego,
// slices 1..3 = UNNORMALIZED activations; g_norm = inverse norms.
__device__ float g_all [(size_t)N_NODES * ROWSTRIDE];    // 102.4 MB
__device__ float g_side[(size_t)N_NODES * EMB];          // 25.6 MB
__device__ float g_norm[(size_t)N_LAYERS * N_NODES];     // 1.2 MB
__device__ float g_acc[2];                                // zero at load; re-zeroed by finalize
// bf16 mirror of CURRENT ego slice: gather table for the SpMM
__device__ __nv_bfloat16 g_ego16[(size_t)N_NODES * EMB]; // 12.8 MB

// CSR build scratch (g_cnt zero at load; re-zeroed by scan2 each launch)
__device__ int  g_cnt[N_NODES];
__device__ int  g_row_ptr[N_NODES + 1];
__device__ int  g_cur[N_NODES];
__device__ int  g_bsum[NBLK];
__device__ int2 g_csr[NNZ];                              // {col, val bits}

__device__ __forceinline__ float4 bf16x4_to_f4(uint2 r) {
    __nv_bfloat162 lo = *(__nv_bfloat162*)&r.x;
    __nv_bfloat162 hi = *(__nv_bfloat162*)&r.y;
    float2 a = __bfloat1622float2(lo), b = __bfloat1622float2(hi);
    return make_float4(a.x, a.y, b.x, b.y);
}

// ---------------------------------------------------------------------------
__global__ void init_kernel(const float* __restrict__ ue, const float* __restrict__ ie) {
    int t = blockIdx.x * 256 + threadIdx.x;              // N_NODES*16 threads
    int node = t >> 4, q = t & 15;
    const float* src = (node < N_USERS) ? (ue + (size_t)node * EMB)
                                        : (ie + (size_t)(node - N_USERS) * EMB);
    float4 v = *(const float4*)(src + q * 4);
    *(float4*)(g_all + (size_t)node * ROWSTRIDE + q * 4) = v;
    __nv_bfloat162* b = (__nv_bfloat162*)(g_ego16 + (size_t)node * EMB + q * 4);
    b[0] = __floats2bfloat162_rn(v.x, v.y);
    b[1] = __floats2bfloat162_rn(v.z, v.w);
}

// ---------------------------------------------------------------------------
// CSR build: histogram -> 2-level exclusive scan -> scatter
// ---------------------------------------------------------------------------
__global__ void hist_kernel(const int* __restrict__ row) {
    int t = blockIdx.x * 256 + threadIdx.x;
    if (t < NNZ) atomicAdd(&g_cnt[__ldg(row + t)], 1);
}

__global__ void scan1_kernel() {
    __shared__ int shw[16];
    int t = threadIdx.x;                                  // 512 threads
    int i = blockIdx.x * SCAN_CHUNK + t;
    int v = (i < N_NODES) ? g_cnt[i] : 0;
    #pragma unroll
    for (int o = 16; o; o >>= 1) v += __shfl_xor_sync(0xffffffffu, v, o);
    if ((t & 31) == 0) shw[t >> 5] = v;
    __syncthreads();
    if (t < 32) {
        int s = (t < 16) ? shw[t] : 0;
        #pragma unroll
        for (int o = 8; o; o >>= 1) s += __shfl_xor_sync(0xffffffffu, s, o);
        if (t == 0) g_bsum[blockIdx.x] = s;
    }
}

__global__ void scanB_kernel() {
    __shared__ int shw[8];
    int t = threadIdx.x;                                  // 256 threads
    int lane = t & 31, w = t >> 5;
    int v = (t < NBLK) ? g_bsum[t] : 0;
    int inc = v;
    #pragma unroll
    for (int o = 1; o < 32; o <<= 1) {
        int n = __shfl_up_sync(0xffffffffu, inc, o);
        if (lane >= o) inc += n;
    }
    if (lane == 31) shw[w] = inc;
    __syncthreads();
    if (t < 32) {
        int s = (t < 8) ? shw[t] : 0;
        #pragma unroll
        for (int o = 1; o < 8; o <<= 1) {
            int n = __shfl_up_sync(0xffffffffu, s, o);
            if (lane >= o) s += n;
        }
        if (t < 8) shw[t] = s;
    }
    __syncthreads();
    int base = (w > 0) ? shw[w - 1] : 0;
    if (t < NBLK) g_bsum[t] = base + inc - v;
}

__global__ void scan2_kernel() {
    __shared__ int shw[16];
    int t = threadIdx.x;                                  // 512 threads
    int lane = t & 31, w = t >> 5;
    int i = blockIdx.x * SCAN_CHUNK + t;
    int v = (i < N_NODES) ? g_cnt[i] : 0;
    int inc = v;
    #pragma unroll
    for (int o = 1; o < 32; o <<= 1) {
        int n = __shfl_up_sync(0xffffffffu, inc, o);
        if (lane >= o) inc += n;
    }
    if (lane == 31) shw[w] = inc;
    __syncthreads();
    if (t < 32) {
        int s = (t < 16) ? shw[t] : 0;
        #pragma unroll
        for (int o = 1; o < 16; o <<= 1) {
            int n = __shfl_up_sync(0xffffffffu, s, o);
            if (lane >= o) s += n;
        }
        if (t < 16) shw[t] = s;
    }
    __syncthreads();
    int base = ((w > 0) ? shw[w - 1] : 0) + g_bsum[blockIdx.x];
    int ex = base + inc - v;
    if (i < N_NODES) {
        g_row_ptr[i] = ex;
        g_cur[i] = ex;
        g_cnt[i] = 0;                                     // re-zero for next replay
    }
    if (i == N_NODES) g_row_ptr[N_NODES] = NNZ;
}

__global__ void scatter_kernel(const int* __restrict__ row,
                               const int* __restrict__ col,
                               const float* __restrict__ val) {
    int t = blockIdx.x * 256 + threadIdx.x;
    if (t >= NNZ) return;
    int r = __ldg(row + t);
    int pos = atomicAdd(&g_cur[r], 1);
    g_csr[pos] = make_int2(__ldg(col + t), __float_as_int(__ldg(val + t)));
}

// ---------------------------------------------------------------------------
// SpMM (CSR gather): one warp per row, HALF-WARP PER EDGE.
// bf16 ego row = 128B = 16 lanes x 8B. Lanes 0-15 handle even edge of each
// pair, 16-31 the odd edge; final shfl_xor(16) combines. 8 edges in flight
// per unrolled step group with only 8 LDG instructions.
// ---------------------------------------------------------------------------
__global__ void __launch_bounds__(256) spmm_csr_kernel() {
    int gt = blockIdx.x * 256 + threadIdx.x;
    int row = gt >> 5, lane = gt & 31;
    if (row >= N_NODES) return;
    int half = lane >> 4;                 // which edge of the pair
    int sub  = lane & 15;                 // 8B chunk within the ego row

    int beg = g_row_ptr[row], end = g_row_ptr[row + 1];
    float4 acc = make_float4(0.f, 0.f, 0.f, 0.f);

    int e = beg;
    for (; e + 8 <= end; e += 8) {        // 8 edges: 4 pair-steps
        int2 c0 = __ldg(&g_csr[e     + half]);
        int2 c1 = __ldg(&g_csr[e + 2 + half]);
        int2 c2 = __ldg(&g_csr[e + 4 + half]);
        int2 c3 = __ldg(&g_csr[e + 6 + half]);
        uint2 r0 = __ldg((const uint2*)(g_ego16 + (size_t)c0.x * EMB) + sub);
        uint2 r1 = __ldg((const uint2*)(g_ego16 + (size_t)c1.x * EMB) + sub);
        uint2 r2 = __ldg((const uint2*)(g_ego16 + (size_t)c2.x * EMB) + sub);
        uint2 r3 = __ldg((const uint2*)(g_ego16 + (size_t)c3.x * EMB) + sub);
        float4 a0 = bf16x4_to_f4(r0), a1 = bf16x4_to_f4(r1);
        float4 a2 = bf16x4_to_f4(r2), a3 = bf16x4_to_f4(r3);
        float v0 = __int_as_float(c0.y), v1 = __int_as_float(c1.y);
        float v2 = __int_as_float(c2.y), v3 = __int_as_float(c3.y);
        acc.x += v0 * a0.x + v1 * a1.x + v2 * a2.x + v3 * a3.x;
        acc.y += v0 * a0.y + v1 * a1.y + v2 * a2.y + v3 * a3.y;
        acc.z += v0 * a0.z + v1 * a1.z + v2 * a2.z + v3 * a3.z;
        acc.w += v0 * a0.w + v1 * a1.w + v2 * a2.w + v3 * a3.w;
    }
    for (; e + 2 <= end; e += 2) {        // remaining pairs
        int2 c = __ldg(&g_csr[e + half]);
        uint2 r = __ldg((const uint2*)(g_ego16 + (size_t)c.x * EMB) + sub);
        float4 a = bf16x4_to_f4(r);
        float v = __int_as_float(c.y);
        acc.x += v * a.x; acc.y += v * a.y; acc.z += v * a.z; acc.w += v * a.w;
    }
    if (e < end && half == 0) {           // odd leftover: half 0 only
        int2 c = __ldg(&g_csr[e]);
        uint2 r = __ldg((const uint2*)(g_ego16 + (size_t)c.x * EMB) + sub);
        float4 a = bf16x4_to_f4(r);
        float v = __int_as_float(c.y);
        acc.x += v * a.x; acc.y += v * a.y; acc.z += v * a.z; acc.w += v * a.w;
    }

    // combine halves (lanes l and l+16 hold the same 4 columns)
    acc.x += __shfl_xor_sync(0xffffffffu, acc.x, 16);
    acc.y += __shfl_xor_sync(0xffffffffu, acc.y, 16);
    acc.z += __shfl_xor_sync(0xffffffffu, acc.z, 16);
    acc.w += __shfl_xor_sync(0xffffffffu, acc.w, 16);
    if (half == 0)
        *(float4*)(g_side + (size_t)row * EMB + sub * 4) = acc;
}

// ---------------------------------------------------------------------------
// Transform: act = leaky_relu(side@Wg + ego*(side-ego)@Wb + b)
// Writes UNNORMALIZED act to g_all slice k+1, inverse norm to g_norm,
// and refreshes the bf16 ego mirror for the next layer's SpMM.
// ---------------------------------------------------------------------------
#define TR_SMEM (2048 * 16 + 64 * 4 + 4096 * 8)

__global__ void __launch_bounds__(256) transform_kernel(
        const float* __restrict__ Wg, const float* __restrict__ bg,
        const float* __restrict__ Wb, const float* __restrict__ bb, int k) {
    extern __shared__ float sh[];
    float4* shW4 = (float4*)sh;
    float*  shB  = sh + 2048 * 4;
    float2* shX  = (float2*)(shB + 64);

    int tid = threadIdx.x;
    const float* Wg_k = Wg + k * 4096;
    const float* Wb_k = Wb + k * 4096;
    #pragma unroll
    for (int idx = tid; idx < 2048; idx += 256) {
        int j = idx >> 5, l = idx & 31;
        float2 g = *(const float2*)(Wg_k + j * 64 + l * 2);
        float2 b = *(const float2*)(Wb_k + j * 64 + l * 2);
        shW4[idx] = make_float4(g.x, g.y, b.x, b.y);
    }
    if (tid < 64) shB[tid] = bg[k * 64 + tid] + bb[k * 64 + tid];
    __syncthreads();

    int warp = tid >> 5, lane = tid & 31;
    int rowbase = (blockIdx.x * 8 + warp) * 8;
    float2* shXw = shX + warp * 512;
    const float* ego = g_all + k * EMB;

    #pragma unroll
    for (int r = 0; r < 8; r++) {
        int row = rowbase + r;
        float2 x1 = make_float2(0.f, 0.f), x2 = make_float2(0.f, 0.f);
        if (row < N_NODES) {
            float2 s = *(const float2*)(g_side + (size_t)row * EMB + lane * 2);
            float2 e = *(const float2*)(ego + (size_t)row * ROWSTRIDE + lane * 2);
            x1 = s;
            x2 = make_float2(e.x * (s.x - e.x), e.y * (s.y - e.y));
        }
        ((float4*)(shXw + r * 64))[lane] = make_float4(x1.x, x2.x, x1.y, x2.y);
    }
    __syncwarp();

    float bx = shB[2 * lane], by = shB[2 * lane + 1];
    float2 acc[8];
    #pragma unroll
    for (int r = 0; r < 8; r++) acc[r] = make_float2(bx, by);

    #pragma unroll 4
    for (int j = 0; j < 64; j++) {
        float4 w = shW4[j * 32 + lane];
        #pragma unroll
        for (int r = 0; r < 8; r++) {
            float2 x = shXw[r * 64 + j];
            acc[r].x += x.x * w.x + x.y * w.z;
            acc[r].y += x.x * w.y + x.y * w.w;
        }
    }

    #pragma unroll
    for (int r = 0; r < 8; r++) {
        int row = rowbase + r;
        float v0 = acc[r].x, v1 = acc[r].y;
        v0 = (v0 >= 0.f) ? v0 : 0.01f * v0;
        v1 = (v1 >= 0.f) ? v1 : 0.01f * v1;
        float p = v0 * v0 + v1 * v1;
        #pragma unroll
        for (int o = 16; o; o >>= 1) p += __shfl_xor_sync(0xffffffffu, p, o);
        float inv = 1.f / fmaxf(sqrtf(p), 1e-12f);
        if (row < N_NODES) {
            *(float2*)(g_all + (size_t)row * ROWSTRIDE + (k + 1) * EMB + lane * 2)
                = make_float2(v0, v1);
            if (k < N_LAYERS - 1)
                *(__nv_bfloat162*)(g_ego16 + (size_t)row * EMB + lane * 2)
                    = __floats2bfloat162_rn(v0, v1);
            if (lane == 0) g_norm[(size_t)k * N_NODES + row] = inv;
        }
    }
}

// ---------------------------------------------------------------------------
// BPR loss: one warp per batch element; norms applied on the fly.
// ---------------------------------------------------------------------------
__global__ void loss_kernel(const int* __restrict__ u,
                            const int* __restrict__ ii,
                            const int* __restrict__ jj) {
    int warp = threadIdx.x >> 5, lane = threadIdx.x & 31;
    int b = blockIdx.x * 4 + warp;
    int un = u[b], pn = N_USERS + ii[b], nn = N_USERS + jj[b];
    const float* ur = g_all + (size_t)un * ROWSTRIDE;
    const float* pr = g_all + (size_t)pn * ROWSTRIDE;
    const float* nr = g_all + (size_t)nn * ROWSTRIDE;

    float iu[4], ip[4], in_[4];
    iu[0] = ip[0] = in_[0] = 1.f;
    #pragma unroll
    for (int s = 1; s < 4; s++) {
        iu[s]  = __ldg(&g_norm[(size_t)(s - 1) * N_NODES + un]);
        ip[s]  = __ldg(&g_norm[(size_t)(s - 1) * N_NODES + pn]);
        in_[s] = __ldg(&g_norm[(size_t)(s - 1) * N_NODES + nn]);
    }

    float dui = 0.f, duj = 0.f, l2 = 0.f;
    #pragma unroll
    for (int s = 0; s < 4; s++) {
        float2 uv = *(const float2*)(ur + s * EMB + lane * 2);
        float2 pv = *(const float2*)(pr + s * EMB + lane * 2);
        float2 nv = *(const float2*)(nr + s * EMB + lane * 2);
        uv.x *= iu[s];  uv.y *= iu[s];
        pv.x *= ip[s];  pv.y *= ip[s];
        nv.x *= in_[s]; nv.y *= in_[s];
        dui += uv.x * pv.x + uv.y * pv.y;
        duj += uv.x * nv.x + uv.y * nv.y;
        l2  += uv.x * uv.x + uv.y * uv.y
             + pv.x * pv.x + pv.y * pv.y
             + nv.x * nv.x + nv.y * nv.y;
    }
    #pragma unroll
    for (int o = 16; o; o >>= 1) {
        dui += __shfl_xor_sync(0xffffffffu, dui, o);
        duj += __shfl_xor_sync(0xffffffffu, duj, o);
        l2  += __shfl_xor_sync(0xffffffffu, l2,  o);
    }
    if (lane == 0) {
        float diff = dui - duj;
        float lp = fminf(diff, 0.f) - log1pf(expf(-fabsf(diff)));
        atomicAdd(&g_acc[0], lp);
        atomicAdd(&g_acc[1], 0.5f * l2);
    }
}

__global__ void finalize_kernel(float* out) {
    out[0] = -g_acc[0] / (float)BATCH + REG_L2 * (g_acc[1] / (float)BATCH);
    g_acc[0] = 0.f;                                       // re-zero for next replay
    g_acc[1] = 0.f;
}

// ---------------------------------------------------------------------------
extern "C" void kernel_launch(void* const* d_in, const int* in_sizes, int n_in,
                              void* d_out, int out_size) {
    const float* user_emb = (const float*)d_in[0];
    const float* item_emb = (const float*)d_in[1];
    const float* W_gc     = (const float*)d_in[2];
    const float* b_gc     = (const float*)d_in[3];
    const float* W_bi     = (const float*)d_in[4];
    const float* b_bi     = (const float*)d_in[5];
    const float* adj_val  = (const float*)d_in[6];
    const int*   adj_row  = (const int*)d_in[7];
    const int*   adj_col  = (const int*)d_in[8];
    const int*   u        = (const int*)d_in[9];
    const int*   i        = (const int*)d_in[10];
    const int*   j        = (const int*)d_in[11];
    float* out = (float*)d_out;

    static bool configured = false;
    if (!configured) {
        configured = true;
        cudaFuncSetAttribute(transform_kernel,
                             cudaFuncAttributeMaxDynamicSharedMemorySize, TR_SMEM);
    }

    init_kernel<<<(N_NODES * 16) / 256, 256>>>(user_emb, item_emb);

    // ---- CSR build (once; reused by all 3 layers) ----
    hist_kernel<<<(NNZ + 255) / 256, 256>>>(adj_row);
    scan1_kernel<<<NBLK, SCAN_CHUNK>>>();
    scanB_kernel<<<1, 256>>>();
    scan2_kernel<<<NBLK, SCAN_CHUNK>>>();
    scatter_kernel<<<(NNZ + 255) / 256, 256>>>(adj_row, adj_col, adj_val);

    for (int k = 0; k < N_LAYERS; k++) {
        spmm_csr_kernel<<<(N_NODES * 32 + 255) / 256, 256>>>();
        transform_kernel<<<(N_NODES + 63) / 64, 256, TR_SMEM>>>(W_gc, b_gc, W_bi, b_bi, k);
    }

    loss_kernel<<<BATCH / 4, 128>>>(u, i, j);
    finalize_kernel<<<1, 1>>>(out);
}

// round 7
// speedup vs baseline: 1.1574x; 1.0997x over previous
#include <cuda_runtime.h>
#include <cuda_bf16.h>

#define N_USERS 50000
#define N_ITEMS 50000
#define N_NODES 100000
#define NNZ     1600000
#define EMB     64
#define N_LAYERS 3
#define BATCH   4096
#define REG_L2  1e-5f

#define SCAN_CHUNK 512
#define NBLK ((N_NODES + SCAN_CHUNK - 1) / SCAN_CHUNK)   // 196
#define ROWSTRIDE (EMB * (N_LAYERS + 1))                 // 256

// all_emb: [node][256]; slice k = cols [64k,64k+64). Slice 0 = raw ego,
// slices 1..3 = UNNORMALIZED activations; g_norm = inverse norms.
__device__ float g_all [(size_t)N_NODES * ROWSTRIDE];    // 102.4 MB
__device__ float g_side[(size_t)N_NODES * EMB];          // 25.6 MB
__device__ float g_norm[(size_t)N_LAYERS * N_NODES];     // 1.2 MB
__device__ float g_acc[2];                                // zero at load; re-zeroed by finalize
// bf16 mirror of CURRENT ego slice: gather table for the SpMM
__device__ __nv_bfloat16 g_ego16[(size_t)N_NODES * EMB]; // 12.8 MB

// CSR build scratch (g_cnt zero at load; re-zeroed by scan2 each launch)
__device__ int  g_cnt[N_NODES];
__device__ int  g_row_ptr[N_NODES + 1];
__device__ int  g_cur[N_NODES];
__device__ int  g_bsum[NBLK];
__device__ int2 g_csr[NNZ];                              // {col, val bits}

__device__ __forceinline__ float4 bf16x4_to_f4(uint2 r) {
    __nv_bfloat162 lo = *(__nv_bfloat162*)&r.x;
    __nv_bfloat162 hi = *(__nv_bfloat162*)&r.y;
    float2 a = __bfloat1622float2(lo), b = __bfloat1622float2(hi);
    return make_float4(a.x, a.y, b.x, b.y);
}

// ---- packed fp32x2 helpers (sm_103a) ----
__device__ __forceinline__ unsigned long long splat2(float f) {
    unsigned long long d;
    unsigned int b = __float_as_uint(f);
    asm("mov.b64 %0, {%1, %1};" : "=l"(d) : "r"(b));
    return d;
}
#define FMA2(acc, a, b) \
    asm("fma.rn.f32x2 %0, %1, %2, %0;" : "+l"(acc) : "l"(a), "l"(b))
__device__ __forceinline__ float2 unpack2(unsigned long long v) {
    unsigned int lo, hi;
    asm("mov.b64 {%0, %1}, %2;" : "=r"(lo), "=r"(hi) : "l"(v));
    return make_float2(__uint_as_float(lo), __uint_as_float(hi));
}

// ---------------------------------------------------------------------------
__global__ void init_kernel(const float* __restrict__ ue, const float* __restrict__ ie) {
    int t = blockIdx.x * 256 + threadIdx.x;              // N_NODES*16 threads
    int node = t >> 4, q = t & 15;
    const float* src = (node < N_USERS) ? (ue + (size_t)node * EMB)
                                        : (ie + (size_t)(node - N_USERS) * EMB);
    float4 v = *(const float4*)(src + q * 4);
    *(float4*)(g_all + (size_t)node * ROWSTRIDE + q * 4) = v;
    __nv_bfloat162* b = (__nv_bfloat162*)(g_ego16 + (size_t)node * EMB + q * 4);
    b[0] = __floats2bfloat162_rn(v.x, v.y);
    b[1] = __floats2bfloat162_rn(v.z, v.w);
}

// ---------------------------------------------------------------------------
// CSR build: histogram -> 2-level exclusive scan -> scatter
// ---------------------------------------------------------------------------
__global__ void hist_kernel(const int* __restrict__ row) {
    int t = blockIdx.x * 256 + threadIdx.x;
    if (t < NNZ) atomicAdd(&g_cnt[__ldg(row + t)], 1);
}

__global__ void scan1_kernel() {
    __shared__ int shw[16];
    int t = threadIdx.x;                                  // 512 threads
    int i = blockIdx.x * SCAN_CHUNK + t;
    int v = (i < N_NODES) ? g_cnt[i] : 0;
    #pragma unroll
    for (int o = 16; o; o >>= 1) v += __shfl_xor_sync(0xffffffffu, v, o);
    if ((t & 31) == 0) shw[t >> 5] = v;
    __syncthreads();
    if (t < 32) {
        int s = (t < 16) ? shw[t] : 0;
        #pragma unroll
        for (int o = 8; o; o >>= 1) s += __shfl_xor_sync(0xffffffffu, s, o);
        if (t == 0) g_bsum[blockIdx.x] = s;
    }
}

__global__ void scanB_kernel() {
    __shared__ int shw[8];
    int t = threadIdx.x;                                  // 256 threads
    int lane = t & 31, w = t >> 5;
    int v = (t < NBLK) ? g_bsum[t] : 0;
    int inc = v;
    #pragma unroll
    for (int o = 1; o < 32; o <<= 1) {
        int n = __shfl_up_sync(0xffffffffu, inc, o);
        if (lane >= o) inc += n;
    }
    if (lane == 31) shw[w] = inc;
    __syncthreads();
    if (t < 32) {
        int s = (t < 8) ? shw[t] : 0;
        #pragma unroll
        for (int o = 1; o < 8; o <<= 1) {
            int n = __shfl_up_sync(0xffffffffu, s, o);
            if (lane >= o) s += n;
        }
        if (t < 8) shw[t] = s;
    }
    __syncthreads();
    int base = (w > 0) ? shw[w - 1] : 0;
    if (t < NBLK) g_bsum[t] = base + inc - v;
}

__global__ void scan2_kernel() {
    __shared__ int shw[16];
    int t = threadIdx.x;                                  // 512 threads
    int lane = t & 31, w = t >> 5;
    int i = blockIdx.x * SCAN_CHUNK + t;
    int v = (i < N_NODES) ? g_cnt[i] : 0;
    int inc = v;
    #pragma unroll
    for (int o = 1; o < 32; o <<= 1) {
        int n = __shfl_up_sync(0xffffffffu, inc, o);
        if (lane >= o) inc += n;
    }
    if (lane == 31) shw[w] = inc;
    __syncthreads();
    if (t < 32) {
        int s = (t < 16) ? shw[t] : 0;
        #pragma unroll
        for (int o = 1; o < 16; o <<= 1) {
            int n = __shfl_up_sync(0xffffffffu, s, o);
            if (lane >= o) s += n;
        }
        if (t < 16) shw[t] = s;
    }
    __syncthreads();
    int base = ((w > 0) ? shw[w - 1] : 0) + g_bsum[blockIdx.x];
    int ex = base + inc - v;
    if (i < N_NODES) {
        g_row_ptr[i] = ex;
        g_cur[i] = ex;
        g_cnt[i] = 0;                                     // re-zero for next replay
    }
    if (i == N_NODES) g_row_ptr[N_NODES] = NNZ;
}

__global__ void scatter_kernel(const int* __restrict__ row,
                               const int* __restrict__ col,
                               const float* __restrict__ val) {
    int t = blockIdx.x * 256 + threadIdx.x;
    if (t >= NNZ) return;
    int r = __ldg(row + t);
    int pos = atomicAdd(&g_cur[r], 1);
    g_csr[pos] = make_int2(__ldg(col + t), __float_as_int(__ldg(val + t)));
}

// ---------------------------------------------------------------------------
// SpMM (CSR gather): one warp per row, half-warp per edge (round-6 proven).
// ---------------------------------------------------------------------------
__global__ void __launch_bounds__(256) spmm_csr_kernel() {
    int gt = blockIdx.x * 256 + threadIdx.x;
    int row = gt >> 5, lane = gt & 31;
    if (row >= N_NODES) return;
    int half = lane >> 4;
    int sub  = lane & 15;

    int beg = g_row_ptr[row], end = g_row_ptr[row + 1];
    float4 acc = make_float4(0.f, 0.f, 0.f, 0.f);

    int e = beg;
    for (; e + 8 <= end; e += 8) {
        int2 c0 = __ldg(&g_csr[e     + half]);
        int2 c1 = __ldg(&g_csr[e + 2 + half]);
        int2 c2 = __ldg(&g_csr[e + 4 + half]);
        int2 c3 = __ldg(&g_csr[e + 6 + half]);
        uint2 r0 = __ldg((const uint2*)(g_ego16 + (size_t)c0.x * EMB) + sub);
        uint2 r1 = __ldg((const uint2*)(g_ego16 + (size_t)c1.x * EMB) + sub);
        uint2 r2 = __ldg((const uint2*)(g_ego16 + (size_t)c2.x * EMB) + sub);
        uint2 r3 = __ldg((const uint2*)(g_ego16 + (size_t)c3.x * EMB) + sub);
        float4 a0 = bf16x4_to_f4(r0), a1 = bf16x4_to_f4(r1);
        float4 a2 = bf16x4_to_f4(r2), a3 = bf16x4_to_f4(r3);
        float v0 = __int_as_float(c0.y), v1 = __int_as_float(c1.y);
        float v2 = __int_as_float(c2.y), v3 = __int_as_float(c3.y);
        acc.x += v0 * a0.x + v1 * a1.x + v2 * a2.x + v3 * a3.x;
        acc.y += v0 * a0.y + v1 * a1.y + v2 * a2.y + v3 * a3.y;
        acc.z += v0 * a0.z + v1 * a1.z + v2 * a2.z + v3 * a3.z;
        acc.w += v0 * a0.w + v1 * a1.w + v2 * a2.w + v3 * a3.w;
    }
    for (; e + 2 <= end; e += 2) {
        int2 c = __ldg(&g_csr[e + half]);
        uint2 r = __ldg((const uint2*)(g_ego16 + (size_t)c.x * EMB) + sub);
        float4 a = bf16x4_to_f4(r);
        float v = __int_as_float(c.y);
        acc.x += v * a.x; acc.y += v * a.y; acc.z += v * a.z; acc.w += v * a.w;
    }
    if (e < end && half == 0) {
        int2 c = __ldg(&g_csr[e]);
        uint2 r = __ldg((const uint2*)(g_ego16 + (size_t)c.x * EMB) + sub);
        float4 a = bf16x4_to_f4(r);
        float v = __int_as_float(c.y);
        acc.x += v * a.x; acc.y += v * a.y; acc.z += v * a.z; acc.w += v * a.w;
    }

    acc.x += __shfl_xor_sync(0xffffffffu, acc.x, 16);
    acc.y += __shfl_xor_sync(0xffffffffu, acc.y, 16);
    acc.z += __shfl_xor_sync(0xffffffffu, acc.z, 16);
    acc.w += __shfl_xor_sync(0xffffffffu, acc.w, 16);
    if (half == 0)
        *(float4*)(g_side + (size_t)row * EMB + sub * 4) = acc;
}

// ---------------------------------------------------------------------------
// Transform with packed fp32x2 FMAs.
// Row-pair blocking: acc0[rp] holds col 2l for rows (2rp, 2rp+1) packed;
// acc1[rp] holds col 2l+1. Staging layout per warp:
//   shXp[rp*64 + j] = {x1[2rp][j], x1[2rp+1][j], x2[2rp][j], x2[2rp+1][j]}
// Inner loop per j: 1 W LDS.128 + 4 splats + 4 x LDS.128 + 16 fma.rn.f32x2.
// ---------------------------------------------------------------------------
#define TR_SMEM (2048 * 16 + 64 * 4 + 4096 * 8)

__global__ void __launch_bounds__(256) transform_kernel(
        const float* __restrict__ Wg, const float* __restrict__ bg,
        const float* __restrict__ Wb, const float* __restrict__ bb, int k) {
    extern __shared__ float sh[];
    float4* shW4 = (float4*)sh;                   // [j*32+lane] = {Wg[j][2l],Wg[j][2l+1],Wb[j][2l],Wb[j][2l+1]}
    float*  shB  = sh + 2048 * 4;
    float4* shXp = (float4*)(shB + 64);           // [warp][rp*64 + j]

    int tid = threadIdx.x;
    const float* Wg_k = Wg + k * 4096;
    const float* Wb_k = Wb + k * 4096;
    #pragma unroll
    for (int idx = tid; idx < 2048; idx += 256) {
        int j = idx >> 5, l = idx & 31;
        float2 g = *(const float2*)(Wg_k + j * 64 + l * 2);
        float2 b = *(const float2*)(Wb_k + j * 64 + l * 2);
        shW4[idx] = make_float4(g.x, g.y, b.x, b.y);
    }
    if (tid < 64) shB[tid] = bg[k * 64 + tid] + bb[k * 64 + tid];
    __syncthreads();

    int warp = tid >> 5, lane = tid & 31;
    int rowbase = (blockIdx.x * 8 + warp) * 8;
    float4* shXw = shXp + warp * 256;             // 4 row-pairs * 64 j
    const float* ego = g_all + k * EMB;

    // Stage: process rows in pairs; lane owns j = 2l, 2l+1.
    #pragma unroll
    for (int rp = 0; rp < 4; rp++) {
        float2 x1e = make_float2(0.f, 0.f), x2e = x1e;
        float2 x1o = x1e, x2o = x1e;
        int re = rowbase + 2 * rp, ro = re + 1;
        if (re < N_NODES) {
            float2 s = *(const float2*)(g_side + (size_t)re * EMB + lane * 2);
            float2 e = *(const float2*)(ego + (size_t)re * ROWSTRIDE + lane * 2);
            x1e = s;
            x2e = make_float2(e.x * (s.x - e.x), e.y * (s.y - e.y));
        }
        if (ro < N_NODES) {
            float2 s = *(const float2*)(g_side + (size_t)ro * EMB + lane * 2);
            float2 e = *(const float2*)(ego + (size_t)ro * ROWSTRIDE + lane * 2);
            x1o = s;
            x2o = make_float2(e.x * (s.x - e.x), e.y * (s.y - e.y));
        }
        shXw[rp * 64 + 2 * lane]     = make_float4(x1e.x, x1o.x, x2e.x, x2o.x);
        shXw[rp * 64 + 2 * lane + 1] = make_float4(x1e.y, x1o.y, x2e.y, x2o.y);
    }
    __syncwarp();

    unsigned long long acc0[4], acc1[4];
    {
        unsigned long long b0 = splat2(shB[2 * lane]);
        unsigned long long b1 = splat2(shB[2 * lane + 1]);
        #pragma unroll
        for (int rp = 0; rp < 4; rp++) { acc0[rp] = b0; acc1[rp] = b1; }
    }

    const ulonglong2* shXw2 = (const ulonglong2*)shXw;
    #pragma unroll 4
    for (int j = 0; j < 64; j++) {
        float4 w = shW4[j * 32 + lane];
        unsigned long long wg0 = splat2(w.x), wg1 = splat2(w.y);
        unsigned long long wb0 = splat2(w.z), wb1 = splat2(w.w);
        #pragma unroll
        for (int rp = 0; rp < 4; rp++) {
            ulonglong2 xp = shXw2[rp * 64 + j];   // .x = x1 pair, .y = x2 pair
            FMA2(acc0[rp], xp.x, wg0);
            FMA2(acc0[rp], xp.y, wb0);
            FMA2(acc1[rp], xp.x, wg1);
            FMA2(acc1[rp], xp.y, wb1);
        }
    }

    // Epilogue: unpack row pairs, leaky-relu, norm, store.
    #pragma unroll
    for (int rp = 0; rp < 4; rp++) {
        float2 c0 = unpack2(acc0[rp]);            // (row even, row odd) @ col 2l
        float2 c1 = unpack2(acc1[rp]);            // @ col 2l+1
        #pragma unroll
        for (int odd = 0; odd < 2; odd++) {
            int row = rowbase + 2 * rp + odd;
            float v0 = odd ? c0.y : c0.x;
            float v1 = odd ? c1.y : c1.x;
            v0 = (v0 >= 0.f) ? v0 : 0.01f * v0;
            v1 = (v1 >= 0.f) ? v1 : 0.01f * v1;
            float p = v0 * v0 + v1 * v1;
            #pragma unroll
            for (int o = 16; o; o >>= 1) p += __shfl_xor_sync(0xffffffffu, p, o);
            float inv = 1.f / fmaxf(sqrtf(p), 1e-12f);
            if (row < N_NODES) {
                *(float2*)(g_all + (size_t)row * ROWSTRIDE + (k + 1) * EMB + lane * 2)
                    = make_float2(v0, v1);
                if (k < N_LAYERS - 1)
                    *(__nv_bfloat162*)(g_ego16 + (size_t)row * EMB + lane * 2)
                        = __floats2bfloat162_rn(v0, v1);
                if (lane == 0) g_norm[(size_t)k * N_NODES + row] = inv;
            }
        }
    }
}

// ---------------------------------------------------------------------------
// BPR loss: one warp per batch element; norms applied on the fly.
// ---------------------------------------------------------------------------
__global__ void loss_kernel(const int* __restrict__ u,
                            const int* __restrict__ ii,
                            const int* __restrict__ jj) {
    int warp = threadIdx.x >> 5, lane = threadIdx.x & 31;
    int b = blockIdx.x * 4 + warp;
    int un = u[b], pn = N_USERS + ii[b], nn = N_USERS + jj[b];
    const float* ur = g_all + (size_t)un * ROWSTRIDE;
    const float* pr = g_all + (size_t)pn * ROWSTRIDE;
    const float* nr = g_all + (size_t)nn * ROWSTRIDE;

    float iu[4], ip[4], in_[4];
    iu[0] = ip[0] = in_[0] = 1.f;
    #pragma unroll
    for (int s = 1; s < 4; s++) {
        iu[s]  = __ldg(&g_norm[(size_t)(s - 1) * N_NODES + un]);
        ip[s]  = __ldg(&g_norm[(size_t)(s - 1) * N_NODES + pn]);
        in_[s] = __ldg(&g_norm[(size_t)(s - 1) * N_NODES + nn]);
    }

    float dui = 0.f, duj = 0.f, l2 = 0.f;
    #pragma unroll
    for (int s = 0; s < 4; s++) {
        float2 uv = *(const float2*)(ur + s * EMB + lane * 2);
        float2 pv = *(const float2*)(pr + s * EMB + lane * 2);
        float2 nv = *(const float2*)(nr + s * EMB + lane * 2);
        uv.x *= iu[s];  uv.y *= iu[s];
        pv.x *= ip[s];  pv.y *= ip[s];
        nv.x *= in_[s]; nv.y *= in_[s];
        dui += uv.x * pv.x + uv.y * pv.y;
        duj += uv.x * nv.x + uv.y * nv.y;
        l2  += uv.x * uv.x + uv.y * uv.y
             + pv.x * pv.x + pv.y * pv.y
             + nv.x * nv.x + nv.y * nv.y;
    }
    #pragma unroll
    for (int o = 16; o; o >>= 1) {
        dui += __shfl_xor_sync(0xffffffffu, dui, o);
        duj += __shfl_xor_sync(0xffffffffu, duj, o);
        l2  += __shfl_xor_sync(0xffffffffu, l2,  o);
    }
    if (lane == 0) {
        float diff = dui - duj;
        float lp = fminf(diff, 0.f) - log1pf(expf(-fabsf(diff)));
        atomicAdd(&g_acc[0], lp);
        atomicAdd(&g_acc[1], 0.5f * l2);
    }
}

__global__ void finalize_kernel(float* out) {
    out[0] = -g_acc[0] / (float)BATCH + REG_L2 * (g_acc[1] / (float)BATCH);
    g_acc[0] = 0.f;
    g_acc[1] = 0.f;
}

// ---------------------------------------------------------------------------
extern "C" void kernel_launch(void* const* d_in, const int* in_sizes, int n_in,
                              void* d_out, int out_size) {
    const float* user_emb = (const float*)d_in[0];
    const float* item_emb = (const float*)d_in[1];
    const float* W_gc     = (const float*)d_in[2];
    const float* b_gc     = (const float*)d_in[3];
    const float* W_bi     = (const float*)d_in[4];
    const float* b_bi     = (const float*)d_in[5];
    const float* adj_val  = (const float*)d_in[6];
    const int*   adj_row  = (const int*)d_in[7];
    const int*   adj_col  = (const int*)d_in[8];
    const int*   u        = (const int*)d_in[9];
    const int*   i        = (const int*)d_in[10];
    const int*   j        = (const int*)d_in[11];
    float* out = (float*)d_out;

    static bool configured = false;
    if (!configured) {
        configured = true;
        cudaFuncSetAttribute(transform_kernel,
                             cudaFuncAttributeMaxDynamicSharedMemorySize, TR_SMEM);
    }

    init_kernel<<<(N_NODES * 16) / 256, 256>>>(user_emb, item_emb);

    // ---- CSR build (once; reused by all 3 layers) ----
    hist_kernel<<<(NNZ + 255) / 256, 256>>>(adj_row);
    scan1_kernel<<<NBLK, SCAN_CHUNK>>>();
    scanB_kernel<<<1, 256>>>();
    scan2_kernel<<<NBLK, SCAN_CHUNK>>>();
    scatter_kernel<<<(NNZ + 255) / 256, 256>>>(adj_row, adj_col, adj_val);

    for (int k = 0; k < N_LAYERS; k++) {
        spmm_csr_kernel<<<(N_NODES * 32 + 255) / 256, 256>>>();
        transform_kernel<<<(N_NODES + 63) / 64, 256, TR_SMEM>>>(W_gc, b_gc, W_bi, b_bi, k);
    }

    loss_kernel<<<BATCH / 4, 128>>>(u, i, j);
    finalize_kernel<<<1, 1>>>(out);
}